// round 10
// baseline (speedup 1.0000x reference)
#include <cuda_runtime.h>

// QuaternionMaxAmpPool2d — round 10: R9 body (2 output pixels/thread, float4
// __ldcs loads, float2 __stcs stores, 40 regs) with 64-thread CTAs and
// __launch_bounds__(64,24): 24 CTAs/SM -> 48/64 warps, finest wave
// granularity. Final occupancy-axis probe; kernel is ~98% of the LTS chip
// cap (~6.9 TB/s) already.
//
// x: (bs, 256, 128, 128) fp32, c = comp*64 + cc. For each 2x2 window,
// amp[k] = sum_comp v[comp][k]^2 (sqrt monotone -> skipped); argmax k
// (first max, matches jnp.argmax); output the 4 component values at that k.
// out: (bs, 256, 64, 64).

__global__ void __launch_bounds__(64, 24) qmax_pool_kernel(
    const float* __restrict__ x, float* __restrict__ out, int total_threads)
{
    int t = blockIdx.x * blockDim.x + threadIdx.x;
    if (t >= total_threads) return;

    // decompose: j = w-pair (covers w2 = 2j, 2j+1), h2, cc, b
    int j  = t & 31;          // 0..31
    int h2 = (t >> 5) & 63;   // 0..63
    int cc = (t >> 11) & 63;  // 0..63
    int b  = t >> 17;

    const long long IN_B_STRIDE  = 256LL * 128 * 128;
    const long long COMP_STRIDE  = 64LL * 128 * 128;
    const long long PLANE_STRIDE = 128LL * 128;

    const float* base = x + (long long)b * IN_B_STRIDE
                          + (long long)cc * PLANE_STRIDE
                          + (long long)(h2 * 2) * 128
                          + (long long)j * 4;

    float4 r0[4], r1[4];
#pragma unroll
    for (int c = 0; c < 4; c++) {
        const float* p = base + (long long)c * COMP_STRIDE;
        r0[c] = __ldcs(reinterpret_cast<const float4*>(p));
        r1[c] = __ldcs(reinterpret_cast<const float4*>(p + 128));
    }

    // window k = kh*2 + kw: k0=(h0,w0) k1=(h0,w1) k2=(h1,w0) k3=(h1,w1)

    // ---- output pixel 0 (w2 = 2j): vals k0=r0.x k1=r0.y k2=r1.x k3=r1.y
    float a0 = 0.f, a1 = 0.f, a2 = 0.f, a3 = 0.f;
#pragma unroll
    for (int c = 0; c < 4; c++) {
        a0 = fmaf(r0[c].x, r0[c].x, a0);
        a1 = fmaf(r0[c].y, r0[c].y, a1);
        a2 = fmaf(r1[c].x, r1[c].x, a2);
        a3 = fmaf(r1[c].y, r1[c].y, a3);
    }
    int k_lo = 0; float m = a0;
    if (a1 > m) { m = a1; k_lo = 1; }
    if (a2 > m) { m = a2; k_lo = 2; }
    if (a3 > m) { m = a3; k_lo = 3; }

    // ---- output pixel 1 (w2 = 2j+1): k0=r0.z k1=r0.w k2=r1.z k3=r1.w
    float b0 = 0.f, b1 = 0.f, b2 = 0.f, b3 = 0.f;
#pragma unroll
    for (int c = 0; c < 4; c++) {
        b0 = fmaf(r0[c].z, r0[c].z, b0);
        b1 = fmaf(r0[c].w, r0[c].w, b1);
        b2 = fmaf(r1[c].z, r1[c].z, b2);
        b3 = fmaf(r1[c].w, r1[c].w, b3);
    }
    int k_hi = 0; float mh = b0;
    if (b1 > mh) { mh = b1; k_hi = 1; }
    if (b2 > mh) { mh = b2; k_hi = 2; }
    if (b3 > mh) { mh = b3; k_hi = 3; }

    const long long OUT_B_STRIDE    = 256LL * 64 * 64;
    const long long OUT_C_STRIDE    = 64LL * 64;
    const long long OUT_COMP_STRIDE = 64LL * OUT_C_STRIDE;
    float* obase = out + (long long)b * OUT_B_STRIDE
                       + (long long)cc * OUT_C_STRIDE
                       + (long long)h2 * 64
                       + (long long)j * 2;

#pragma unroll
    for (int c = 0; c < 4; c++) {
        float v_lo = (k_lo == 0) ? r0[c].x : (k_lo == 1) ? r0[c].y
                   : (k_lo == 2) ? r1[c].x : r1[c].y;
        float v_hi = (k_hi == 0) ? r0[c].z : (k_hi == 1) ? r0[c].w
                   : (k_hi == 2) ? r1[c].z : r1[c].w;
        __stcs(reinterpret_cast<float2*>(obase + (long long)c * OUT_COMP_STRIDE),
               make_float2(v_lo, v_hi));
    }
}

extern "C" void kernel_launch(void* const* d_in, const int* in_sizes, int n_in,
                              void* d_out, int out_size)
{
    const float* x = (const float*)d_in[0];
    float* out = (float*)d_out;

    int bs = in_sizes[0] / (256 * 128 * 128);
    int total_threads = bs * 64 * 64 * 32;  // b * cc * h2 * w-pairs

    int block = 64;
    int grid = (total_threads + block - 1) / block;
    qmax_pool_kernel<<<grid, block>>>(x, out, total_threads);
}

// round 11
// speedup vs baseline: 1.0094x; 1.0094x over previous
#include <cuda_runtime.h>

// QuaternionMaxAmpPool2d — FINAL (= R9, best measured: 51.23 us bench,
// 45.47 us ncu, 6.74 TB/s = ~98% of the B300 LTS chip cap).
//
// Design summary from the session:
//  - 2 output pixels/thread: one float4 per comp per input row (8x 16B loads,
//    warp-coalesced 512B segments), float2 stores per comp.
//  - sqrt skipped (monotone under argmax); first-max tie-break matches
//    jnp.argmax. rel_err = 0.
//  - __ldcs/__stcs streaming hints (neutral but never harmful; data is
//    touched exactly once).
//  - __launch_bounds__(128, 12): 40 regs, 12 CTAs/SM. Measured best
//    operating point; occupancy above ~62% gives nothing (LTS-cap bound,
//    verified across occ 32-66%, persistence, and 4px/thread variants).
//
// x: (bs, 256, 128, 128) fp32, c = comp*64 + cc. For each 2x2 window,
// amp[k] = sum_comp v[comp][k]^2; argmax k; output the 4 component values at
// that k. out: (bs, 256, 64, 64).

__global__ void __launch_bounds__(128, 12) qmax_pool_kernel(
    const float* __restrict__ x, float* __restrict__ out, int total_threads)
{
    int t = blockIdx.x * blockDim.x + threadIdx.x;
    if (t >= total_threads) return;

    // decompose: j = w-pair (covers w2 = 2j, 2j+1), h2, cc, b
    int j  = t & 31;          // 0..31
    int h2 = (t >> 5) & 63;   // 0..63
    int cc = (t >> 11) & 63;  // 0..63
    int b  = t >> 17;

    const long long IN_B_STRIDE  = 256LL * 128 * 128;
    const long long COMP_STRIDE  = 64LL * 128 * 128;
    const long long PLANE_STRIDE = 128LL * 128;

    const float* base = x + (long long)b * IN_B_STRIDE
                          + (long long)cc * PLANE_STRIDE
                          + (long long)(h2 * 2) * 128
                          + (long long)j * 4;

    float4 r0[4], r1[4];
#pragma unroll
    for (int c = 0; c < 4; c++) {
        const float* p = base + (long long)c * COMP_STRIDE;
        r0[c] = __ldcs(reinterpret_cast<const float4*>(p));
        r1[c] = __ldcs(reinterpret_cast<const float4*>(p + 128));
    }

    // window k = kh*2 + kw: k0=(h0,w0) k1=(h0,w1) k2=(h1,w0) k3=(h1,w1)

    // ---- output pixel 0 (w2 = 2j): vals k0=r0.x k1=r0.y k2=r1.x k3=r1.y
    float a0 = 0.f, a1 = 0.f, a2 = 0.f, a3 = 0.f;
#pragma unroll
    for (int c = 0; c < 4; c++) {
        a0 = fmaf(r0[c].x, r0[c].x, a0);
        a1 = fmaf(r0[c].y, r0[c].y, a1);
        a2 = fmaf(r1[c].x, r1[c].x, a2);
        a3 = fmaf(r1[c].y, r1[c].y, a3);
    }
    int k_lo = 0; float m = a0;
    if (a1 > m) { m = a1; k_lo = 1; }
    if (a2 > m) { m = a2; k_lo = 2; }
    if (a3 > m) { m = a3; k_lo = 3; }

    // ---- output pixel 1 (w2 = 2j+1): k0=r0.z k1=r0.w k2=r1.z k3=r1.w
    float b0 = 0.f, b1 = 0.f, b2 = 0.f, b3 = 0.f;
#pragma unroll
    for (int c = 0; c < 4; c++) {
        b0 = fmaf(r0[c].z, r0[c].z, b0);
        b1 = fmaf(r0[c].w, r0[c].w, b1);
        b2 = fmaf(r1[c].z, r1[c].z, b2);
        b3 = fmaf(r1[c].w, r1[c].w, b3);
    }
    int k_hi = 0; float mh = b0;
    if (b1 > mh) { mh = b1; k_hi = 1; }
    if (b2 > mh) { mh = b2; k_hi = 2; }
    if (b3 > mh) { mh = b3; k_hi = 3; }

    const long long OUT_B_STRIDE    = 256LL * 64 * 64;
    const long long OUT_C_STRIDE    = 64LL * 64;
    const long long OUT_COMP_STRIDE = 64LL * OUT_C_STRIDE;
    float* obase = out + (long long)b * OUT_B_STRIDE
                       + (long long)cc * OUT_C_STRIDE
                       + (long long)h2 * 64
                       + (long long)j * 2;

#pragma unroll
    for (int c = 0; c < 4; c++) {
        float v_lo = (k_lo == 0) ? r0[c].x : (k_lo == 1) ? r0[c].y
                   : (k_lo == 2) ? r1[c].x : r1[c].y;
        float v_hi = (k_hi == 0) ? r0[c].z : (k_hi == 1) ? r0[c].w
                   : (k_hi == 2) ? r1[c].z : r1[c].w;
        __stcs(reinterpret_cast<float2*>(obase + (long long)c * OUT_COMP_STRIDE),
               make_float2(v_lo, v_hi));
    }
}

extern "C" void kernel_launch(void* const* d_in, const int* in_sizes, int n_in,
                              void* d_out, int out_size)
{
    const float* x = (const float*)d_in[0];
    float* out = (float*)d_out;

    int bs = in_sizes[0] / (256 * 128 * 128);
    int total_threads = bs * 64 * 64 * 32;  // b * cc * h2 * w-pairs

    int block = 128;
    int grid = (total_threads + block - 1) / block;
    qmax_pool_kernel<<<grid, block>>>(x, out, total_threads);
}